// round 3
// baseline (speedup 1.0000x reference)
#include <cuda_runtime.h>
#include <math.h>

#ifndef M_PI
#define M_PI 3.14159265358979323846
#endif

// Problem constants
#define Bc 256
#define Lc 256
#define Dc 128
#define Hc 2
#define Ec 64
#define NLc 2
#define TOPKc 5
#define NUM_TOTAL_C 100000
#define INV_SQRT_E 0.125f
#define INV_SQRT_2F 0.70710678118654752440f

// ---------------- scratch (static __device__, no allocations) ----------------
__device__ float g_x [Bc*Lc*Dc];
__device__ float g_mask[Bc*Lc];
__device__ float g_qb[Bc*Lc*Dc];
__device__ float g_kb[Bc*Lc*Dc];
__device__ float g_vb[Bc*Lc*Dc];
__device__ float g_qt[Bc*Lc*Dc];
__device__ float g_kt[Bc*Lc*Dc];
__device__ float g_vt[Bc*Lc*Dc];
__device__ float g_S [Bc*Hc*Lc*Lc];          // 33.5M floats (raw scores -> softmax in place)
__device__ float g_mv[Bc*Lc];
__device__ float g_gm[Lc];
__device__ int   g_delays[TOPKc];
__device__ float g_w [Bc*TOPKc];
__device__ float g_sp[Bc*Lc*Dc];
__device__ float g_o [Bc*Lc*Dc];
__device__ float g_a [Bc*Lc*Dc];
__device__ float g_h [Bc*Lc*2*Dc];
__device__ float g_c [Lc];
__device__ float g_Cm[Lc*Lc];

// ---------------- generic strided-batched fp32 GEMM ----------------
// C[m,n] = sum_k A[m,k] * B[m? no: B[k,n] (NN)  or  B[n,k] (transB)
// batch offset: off = (z/zdiv)*s1 + (z%zdiv)*s2   (lets us flatten (b,h))
// fuse: 0 none, 1 += resid (batch==1 only), 2 exact-erf GELU
__global__ void gemm_kernel(const float* __restrict__ A, const float* __restrict__ Bp,
                            float* __restrict__ C,
                            int M, int N, int K,
                            int lda, int ldb, int ldc,
                            int zdiv,
                            long sA1, long sA2, long sB1, long sB2, long sC1, long sC2,
                            int transB,
                            const float* __restrict__ R, int ldr, int fuse)
{
    int z  = blockIdx.z;
    int z1 = z / zdiv, z2 = z - z1 * zdiv;
    A  += z1 * sA1 + z2 * sA2;
    Bp += z1 * sB1 + z2 * sB2;
    C  += z1 * sC1 + z2 * sC2;

    const int BM = 64, BN = 64, BK = 16;
    __shared__ float As[16][64 + 4];
    __shared__ float Bs[16][64 + 4];

    int m0 = blockIdx.x * BM, n0 = blockIdx.y * BN;
    int tid = threadIdx.x;
    int tx = tid & 15, ty = tid >> 4;

    float acc[4][4] = {};

    for (int k0 = 0; k0 < K; k0 += BK) {
        #pragma unroll
        for (int i = tid; i < BM * BK; i += 256) {
            int mi = i >> 4, ki = i & 15;
            As[ki][mi] = A[(size_t)(m0 + mi) * lda + (k0 + ki)];
        }
        if (!transB) {
            #pragma unroll
            for (int i = tid; i < BK * BN; i += 256) {
                int ki = i >> 6, ni = i & 63;
                Bs[ki][ni] = Bp[(size_t)(k0 + ki) * ldb + (n0 + ni)];
            }
        } else {
            #pragma unroll
            for (int i = tid; i < BN * BK; i += 256) {
                int ni = i >> 4, ki = i & 15;
                Bs[ki][ni] = Bp[(size_t)(n0 + ni) * ldb + (k0 + ki)];
            }
        }
        __syncthreads();
        #pragma unroll
        for (int kk = 0; kk < BK; kk++) {
            float a[4], bb[4];
            #pragma unroll
            for (int i = 0; i < 4; i++) a[i]  = As[kk][ty * 4 + i];
            #pragma unroll
            for (int j = 0; j < 4; j++) bb[j] = Bs[kk][tx * 4 + j];
            #pragma unroll
            for (int i = 0; i < 4; i++)
                #pragma unroll
                for (int j = 0; j < 4; j++)
                    acc[i][j] = fmaf(a[i], bb[j], acc[i][j]);
        }
        __syncthreads();
    }

    #pragma unroll
    for (int i = 0; i < 4; i++) {
        int m = m0 + ty * 4 + i;
        #pragma unroll
        for (int j = 0; j < 4; j++) {
            int n = n0 + tx * 4 + j;
            float v = acc[i][j];
            if (fuse == 1)      v += R[(size_t)m * ldr + n];
            else if (fuse == 2) v = v * 0.5f * (1.0f + erff(v * INV_SQRT_2F));
            C[(size_t)m * ldc + n] = v;
        }
    }
}

// ---------------- small kernels ----------------
__global__ void build_x_kernel(const int* __restrict__ paths,
                               const float* __restrict__ ego,
                               const float* __restrict__ pos)
{
    int bl = blockIdx.x;
    int c  = threadIdx.x;
    int p  = paths[bl];
    int l  = bl & (Lc - 1);
    g_x[(size_t)bl * Dc + c] = ego[(size_t)p * Dc + c] + pos[l * Dc + c];
    if (c == 0) g_mask[bl] = (p < NUM_TOTAL_C) ? 0.f : -10000.f;
}

// band-pass impulse response c[n] = irfft(mask)[n], computed in double for exactness
__global__ void build_c_kernel(int left, int right)
{
    int n = threadIdx.x;
    double s = 0.0;
    for (int f = left; f < right; f++) {
        double w;
        if (f == 0)            w = 1.0;
        else if (f == Lc / 2)  w = (n & 1) ? -1.0 : 1.0;
        else                   w = 2.0 * cos(2.0 * M_PI * (double)f * (double)n / (double)Lc);
        s += w;
    }
    g_c[n] = (float)(s / (double)Lc);
}

__global__ void build_C_kernel()
{
    int n = blockIdx.x, m = threadIdx.x;
    g_Cm[n * Lc + m] = g_c[(n - m + Lc) & (Lc - 1)];
}

// mean_value[b,d] = (1/D) sum_{h,n} S[b,h,n,(n-d) mod L]
// coalesced row reads + conflict-free shared atomics
__global__ void meanv_kernel()
{
    int b   = blockIdx.x;
    int tid = threadIdx.x;          // 512 threads
    int h   = tid >> 8;
    int m   = tid & 255;
    __shared__ float sh[Lc];
    if (tid < Lc) sh[tid] = 0.f;
    __syncthreads();
    const float* Sh = g_S + ((size_t)b * Hc + h) * Lc * Lc;
    for (int n = 0; n < Lc; n++) {
        float v = Sh[(size_t)n * Lc + m];
        atomicAdd(&sh[(n - m + Lc) & (Lc - 1)], v);
    }
    __syncthreads();
    if (tid < Lc) g_mv[b * Lc + tid] = sh[tid] * (1.0f / 128.0f);
}

__global__ void gmean_kernel()
{
    int d = threadIdx.x;
    float s = 0.f;
    for (int b = 0; b < Bc; b++) s += g_mv[b * Lc + d];
    g_gm[d] = s * (1.0f / (float)Bc);
}

// top-5 argmax over 256 values, single block, tie -> lower index (matches jax top_k set)
__global__ void topk_kernel()
{
    __shared__ float sv[Lc];
    __shared__ int   si[Lc];
    int t = threadIdx.x;
    float my = g_gm[t];
    for (int it = 0; it < TOPKc; it++) {
        sv[t] = my; si[t] = t;
        __syncthreads();
        for (int s = 128; s > 0; s >>= 1) {
            if (t < s) {
                float v2 = sv[t + s]; int i2 = si[t + s];
                if (v2 > sv[t] || (v2 == sv[t] && i2 < si[t])) { sv[t] = v2; si[t] = i2; }
            }
            __syncthreads();
        }
        int win = si[0];
        if (t == 0) g_delays[it] = win;
        __syncthreads();
        if (t == win) my = -INFINITY;
    }
}

__global__ void wsoft_kernel()
{
    int b = threadIdx.x;   // 256 threads
    float w[TOPKc];
    float mx = -1e30f;
    for (int t = 0; t < TOPKc; t++) {
        w[t] = g_mv[b * Lc + g_delays[t]];
        mx = fmaxf(mx, w[t]);
    }
    float s = 0.f;
    for (int t = 0; t < TOPKc; t++) { w[t] = expf(w[t] - mx); s += w[t]; }
    float inv = 1.0f / s;
    for (int t = 0; t < TOPKc; t++) g_w[b * TOPKc + t] = w[t] * inv;
}

// softmax over key dim (with scale + additive key mask), in place on g_S
__global__ void softmax_kernel()
{
    size_t row = blockIdx.x;                 // (b*H + h)*L + q
    int b = (int)(row / (Hc * Lc));
    float* p = g_S + row * (size_t)Lc;
    int t = threadIdx.x;
    float v = p[t] * INV_SQRT_E + g_mask[b * Lc + t];
    __shared__ float red[Lc];
    red[t] = v; __syncthreads();
    for (int s = 128; s > 0; s >>= 1) { if (t < s) red[t] = fmaxf(red[t], red[t + s]); __syncthreads(); }
    float mx = red[0];
    __syncthreads();
    float e = expf(v - mx);
    red[t] = e; __syncthreads();
    for (int s = 128; s > 0; s >>= 1) { if (t < s) red[t] += red[t + s]; __syncthreads(); }
    float inv = 1.0f / red[0];
    p[t] = e * inv;
}

// out = 0.9 * freq(delay-gathered unfiltered V, weights) + 0.1 * spatial
__global__ void combine_kernel()
{
    int bl = blockIdx.x;
    int c  = threadIdx.x;
    int b  = bl >> 8;
    int l  = bl & 255;
    __shared__ float w[TOPKc];
    __shared__ int   dl[TOPKc];
    if (c < TOPKc) { w[c] = g_w[b * TOPKc + c]; dl[c] = g_delays[c]; }
    __syncthreads();
    float f = 0.f;
    #pragma unroll
    for (int t = 0; t < TOPKc; t++) {
        int ls = (l + dl[t]) & 255;
        f += w[t] * g_vb[((size_t)b * Lc + ls) * Dc + c];
    }
    g_o[(size_t)bl * Dc + c] = 0.9f * f + 0.1f * g_sp[(size_t)bl * Dc + c];
}

__global__ void gather_kernel(const int* __restrict__ lengths, float* __restrict__ out)
{
    int b = blockIdx.x;
    int c = threadIdx.x;
    int l = lengths[b] - 1;
    out[b * Dc + c] = g_x[((size_t)b * Lc + l) * Dc + c];
}

// ---------------- host side ----------------
static inline void launch_gemm(const float* A, const float* Bp, float* C,
                               int M, int N, int K,
                               int lda, int ldb, int ldc,
                               int batch, int zdiv,
                               long sA1, long sA2, long sB1, long sB2, long sC1, long sC2,
                               int transB,
                               const float* R = nullptr, int ldr = 0, int fuse = 0)
{
    dim3 grid(M / 64, N / 64, batch);
    gemm_kernel<<<grid, 256>>>(A, Bp, C, M, N, K, lda, ldb, ldc,
                               zdiv, sA1, sA2, sB1, sB2, sC1, sC2,
                               transB, R, ldr, fuse);
}

extern "C" void kernel_launch(void* const* d_in, const int* in_sizes, int n_in,
                              void* d_out, int out_size)
{
    (void)in_sizes; (void)n_in; (void)out_size;
    const int*   paths   = (const int*)  d_in[0];
    const int*   lengths = (const int*)  d_in[1];
    const float* ego     = (const float*)d_in[4];
    const float* pos     = (const float*)d_in[5];
    const float* Wq      = (const float*)d_in[6];
    const float* Wk      = (const float*)d_in[7];
    const float* Wv      = (const float*)d_in[8];
    const float* Wp      = (const float*)d_in[9];
    const float* F1      = (const float*)d_in[10];
    const float* F2      = (const float*)d_in[11];
    float* out = (float*)d_out;

    float *px, *pq, *pk, *pv, *pqt, *pkt, *pvt, *pS, *psp, *po, *pa, *ph, *pCm;
    cudaGetSymbolAddress((void**)&px,  g_x);
    cudaGetSymbolAddress((void**)&pq,  g_qb);
    cudaGetSymbolAddress((void**)&pk,  g_kb);
    cudaGetSymbolAddress((void**)&pv,  g_vb);
    cudaGetSymbolAddress((void**)&pqt, g_qt);
    cudaGetSymbolAddress((void**)&pkt, g_kt);
    cudaGetSymbolAddress((void**)&pvt, g_vt);
    cudaGetSymbolAddress((void**)&pS,  g_S);
    cudaGetSymbolAddress((void**)&psp, g_sp);
    cudaGetSymbolAddress((void**)&po,  g_o);
    cudaGetSymbolAddress((void**)&pa,  g_a);
    cudaGetSymbolAddress((void**)&ph,  g_h);
    cudaGetSymbolAddress((void**)&pCm, g_Cm);

    const long LD = (long)Lc * Dc;    // 32768
    const long LL = (long)Lc * Lc;    // 65536

    build_x_kernel<<<Bc * Lc, Dc>>>(paths, ego, pos);

    const int lefts[NLc]  = {51, 0};
    const int rights[NLc] = {129, 78};

    for (int k = 0; k < NLc; k++) {
        build_c_kernel<<<1, Lc>>>(lefts[k], rights[k]);
        build_C_kernel<<<Lc, Lc>>>();

        // projections: (B*L, D) @ (D, D)
        launch_gemm(px, Wq + (size_t)k * Dc * Dc, pq, Bc * Lc, Dc, Dc, Dc, Dc, Dc,
                    1, 1, 0, 0, 0, 0, 0, 0, 0);
        launch_gemm(px, Wk + (size_t)k * Dc * Dc, pk, Bc * Lc, Dc, Dc, Dc, Dc, Dc,
                    1, 1, 0, 0, 0, 0, 0, 0, 0);
        launch_gemm(px, Wv + (size_t)k * Dc * Dc, pv, Bc * Lc, Dc, Dc, Dc, Dc, Dc,
                    1, 1, 0, 0, 0, 0, 0, 0, 0);

        // band filter (circulant GEMM): per batch b, C(L,L) @ Y_b(L,D)
        launch_gemm(pCm, pq, pqt, Lc, Dc, Lc, Lc, Dc, Dc,
                    Bc, 1, 0, 0, LD, 0, LD, 0, 0);
        launch_gemm(pCm, pk, pkt, Lc, Dc, Lc, Lc, Dc, Dc,
                    Bc, 1, 0, 0, LD, 0, LD, 0, 0);
        launch_gemm(pCm, pv, pvt, Lc, Dc, Lc, Lc, Dc, Dc,
                    Bc, 1, 0, 0, LD, 0, LD, 0, 0);

        // raw scores: per (b,h), Qt(L,E) @ Kt(L,E)^T
        launch_gemm(pqt, pkt, pS, Lc, Lc, Ec, Dc, Dc, Lc,
                    Bc * Hc, Hc, LD, Ec, LD, Ec, (long)Hc * LL, LL, 1);

        // autocorrelation branch (reads raw scores)
        meanv_kernel<<<Bc, 512>>>();
        gmean_kernel<<<1, Lc>>>();
        topk_kernel<<<1, Lc>>>();
        wsoft_kernel<<<1, Bc>>>();

        // attention softmax (in place), then att @ Vt
        softmax_kernel<<<Bc * Hc * Lc, Lc>>>();
        launch_gemm(pS, pvt, psp, Lc, Ec, Lc, Lc, Dc, Dc,
                    Bc * Hc, Hc, (long)Hc * LL, LL, LD, Ec, LD, Ec, 0);

        // freq + spatial mix
        combine_kernel<<<Bc * Lc, Dc>>>();

        // out @ Wp + x (fused residual)
        launch_gemm(po, Wp + (size_t)k * Dc * Dc, pa, Bc * Lc, Dc, Dc, Dc, Dc, Dc,
                    1, 1, 0, 0, 0, 0, 0, 0, 0, px, Dc, 1);

        // FFN: (a @ F1) -> GELU -> (@ F2) -> new x
        launch_gemm(pa, F1 + (size_t)k * Dc * 2 * Dc, ph, Bc * Lc, 2 * Dc, Dc,
                    Dc, 2 * Dc, 2 * Dc, 1, 1, 0, 0, 0, 0, 0, 0, 0, nullptr, 0, 2);
        launch_gemm(ph, F2 + (size_t)k * 2 * Dc * Dc, px, Bc * Lc, Dc, 2 * Dc,
                    2 * Dc, Dc, Dc, 1, 1, 0, 0, 0, 0, 0, 0, 0);
    }

    gather_kernel<<<Bc, Dc>>>(lengths, out);
}

// round 4
// speedup vs baseline: 2.1436x; 2.1436x over previous
#include <cuda_runtime.h>
#include <math.h>

#ifndef M_PI
#define M_PI 3.14159265358979323846
#endif

// Problem constants
#define Bc 256
#define Lc 256
#define Dc 128
#define Hc 2
#define Ec 64
#define NLc 2
#define TOPKc 5
#define NUM_TOTAL_C 100000
#define INV_SQRT_E 0.125f
#define INV_SQRT_2F 0.70710678118654752440f

// ---------------- scratch (static __device__, no allocations) ----------------
__device__ float g_x [Bc*Lc*Dc];
__device__ float g_mask[Bc*Lc];
__device__ float g_xt[Bc*Lc*Dc];             // C @ x  (band-filtered x)
__device__ float g_vb[Bc*Lc*Dc];             // unfiltered V (for delay-gather branch)
__device__ float g_qt[Bc*Lc*Dc];
__device__ float g_kt[Bc*Lc*Dc];
__device__ float g_vt[Bc*Lc*Dc];
__device__ float g_S [Bc*Hc*Lc*Lc];          // raw scores -> softmax in place
__device__ float g_mv[Bc*Lc];
__device__ float g_gm[Lc];
__device__ int   g_delays[TOPKc];
__device__ float g_w [Bc*TOPKc];
__device__ float g_sp[Bc*Lc*Dc];
__device__ float g_o [Bc*Lc*Dc];
__device__ float g_a [Bc*Lc*Dc];
__device__ float g_h [Bc*Lc*2*Dc];
__device__ float g_c [Lc];
__device__ float g_Cm[Lc*Lc];

// ---------------- high-throughput fp32 SGEMM ----------------
// 128 x BN block tile, 256 threads, 8 x (BN/16) per-thread tile, BK=8,
// double-buffered shared memory with register prefetch.
// C[m,n] = sum_k A[m,k] * (transB ? B[n,k] : B[k,n])
// batch offset: z1 = z/zdiv, z2 = z%zdiv;  ptr += z1*s?1 + z2*s?2
// fuse: 0 none, 1 += R[m,n], 2 exact-erf GELU
// Requirements (all met by our shapes): M%128==0, N%BN==0, K%8==0,
// all leading dims multiples of 4, transB only with BN==128.
template<int BN>
__global__ __launch_bounds__(256, 2)
void sgemm_kernel(const float* __restrict__ A, const float* __restrict__ Bp,
                  float* __restrict__ C,
                  int M, int N, int K,
                  int lda, int ldb, int ldc,
                  int zdiv,
                  long sA1, long sA2, long sB1, long sB2, long sC1, long sC2,
                  int transB,
                  const float* __restrict__ R, int ldr, int fuse)
{
    constexpr int TN = BN / 16;
    (void)M; (void)N;

    int z  = blockIdx.z;
    int z1 = z / zdiv, z2 = z - z1 * zdiv;
    A  += z1 * sA1 + z2 * sA2;
    Bp += z1 * sB1 + z2 * sB2;
    C  += z1 * sC1 + z2 * sC2;

    __shared__ float As[2][8][132];
    __shared__ float Bs[2][8][BN + 4];

    const int tid = threadIdx.x;
    const int tx  = tid & 15;
    const int ty  = tid >> 4;
    const int m0  = blockIdx.x * 128;
    const int n0  = blockIdx.y * BN;

    // --- A tile loader: 128 rows x 8 cols, one float4 per thread ---
    const int arow = tid >> 1;
    const int acol = (tid & 1) << 2;
    const float* Ag = A + (size_t)(m0 + arow) * lda + acol;

    // --- B tile loader ---
    const float* Bg;
    bool bActive = true;
    if (transB) {
        // B is N x K: tile BN rows x 8 cols, scatter-transpose into Bs
        const int nrow = tid >> 1;
        const int kcol = (tid & 1) << 2;
        bActive = (BN == 128) || (tid < 128);
        Bg = Bp + (size_t)(n0 + nrow) * ldb + kcol;
    } else if (BN == 128) {
        // tile 8 rows x 128 cols, one float4 per thread, direct
        Bg = Bp + (size_t)(tid >> 5) * ldb + n0 + ((tid & 31) << 2);
    } else {
        // BN==64: tile 8 rows x 64 cols, one float2 per thread
        Bg = Bp + (size_t)(tid >> 5) * ldb + n0 + ((tid & 31) << 1);
    }

    float4 aR, bR;

    float acc[8][TN];
    #pragma unroll
    for (int i = 0; i < 8; i++)
        #pragma unroll
        for (int j = 0; j < TN; j++) acc[i][j] = 0.f;

    const int nk = K >> 3;

    // prologue: tile 0
    aR = *(const float4*)Ag;
    if (transB) {
        if (bActive) bR = *(const float4*)Bg;
    } else if (BN == 128) {
        bR = *(const float4*)Bg;
    } else {
        float2 t = *(const float2*)Bg;
        bR.x = t.x; bR.y = t.y;
    }
    {
        As[0][acol + 0][arow] = aR.x;
        As[0][acol + 1][arow] = aR.y;
        As[0][acol + 2][arow] = aR.z;
        As[0][acol + 3][arow] = aR.w;
        if (transB) {
            if (bActive) {
                const int nrow = tid >> 1, kcol = (tid & 1) << 2;
                Bs[0][kcol + 0][nrow] = bR.x;
                Bs[0][kcol + 1][nrow] = bR.y;
                Bs[0][kcol + 2][nrow] = bR.z;
                Bs[0][kcol + 3][nrow] = bR.w;
            }
        } else if (BN == 128) {
            *(float4*)&Bs[0][tid >> 5][(tid & 31) << 2] = bR;
        } else {
            Bs[0][tid >> 5][((tid & 31) << 1) + 0] = bR.x;
            Bs[0][tid >> 5][((tid & 31) << 1) + 1] = bR.y;
        }
    }
    __syncthreads();

    int buf = 0;
    for (int kt = 0; kt < nk; kt++) {
        // prefetch next tile into registers
        if (kt + 1 < nk) {
            const int koff = (kt + 1) << 3;
            aR = *(const float4*)(Ag + koff);
            if (transB) {
                if (bActive) bR = *(const float4*)(Bg + koff);
            } else if (BN == 128) {
                bR = *(const float4*)(Bg + (size_t)koff * ldb);
            } else {
                float2 t = *(const float2*)(Bg + (size_t)koff * ldb);
                bR.x = t.x; bR.y = t.y;
            }
        }

        // compute on current buffer
        #pragma unroll
        for (int k = 0; k < 8; k++) {
            float a[8], b[TN];
            *(float4*)&a[0] = *(const float4*)&As[buf][k][ty * 8];
            *(float4*)&a[4] = *(const float4*)&As[buf][k][ty * 8 + 4];
            #pragma unroll
            for (int j = 0; j < TN; j += 4)
                *(float4*)&b[j] = *(const float4*)&Bs[buf][k][tx * TN + j];
            #pragma unroll
            for (int i = 0; i < 8; i++)
                #pragma unroll
                for (int j = 0; j < TN; j++)
                    acc[i][j] = fmaf(a[i], b[j], acc[i][j]);
        }

        // store prefetched tile into the other buffer
        if (kt + 1 < nk) {
            const int nb = buf ^ 1;
            As[nb][acol + 0][arow] = aR.x;
            As[nb][acol + 1][arow] = aR.y;
            As[nb][acol + 2][arow] = aR.z;
            As[nb][acol + 3][arow] = aR.w;
            if (transB) {
                if (bActive) {
                    const int nrow = tid >> 1, kcol = (tid & 1) << 2;
                    Bs[nb][kcol + 0][nrow] = bR.x;
                    Bs[nb][kcol + 1][nrow] = bR.y;
                    Bs[nb][kcol + 2][nrow] = bR.z;
                    Bs[nb][kcol + 3][nrow] = bR.w;
                }
            } else if (BN == 128) {
                *(float4*)&Bs[nb][tid >> 5][(tid & 31) << 2] = bR;
            } else {
                Bs[nb][tid >> 5][((tid & 31) << 1) + 0] = bR.x;
                Bs[nb][tid >> 5][((tid & 31) << 1) + 1] = bR.y;
            }
            __syncthreads();
            buf = nb;
        }
    }

    // epilogue
    #pragma unroll
    for (int i = 0; i < 8; i++) {
        const int m = m0 + ty * 8 + i;
        #pragma unroll
        for (int j = 0; j < TN; j += 4) {
            const int n = n0 + tx * TN + j;
            float4 v = *(float4*)&acc[i][j];
            if (fuse == 1) {
                float4 r = *(const float4*)&R[(size_t)m * ldr + n];
                v.x += r.x; v.y += r.y; v.z += r.z; v.w += r.w;
            } else if (fuse == 2) {
                v.x = v.x * 0.5f * (1.0f + erff(v.x * INV_SQRT_2F));
                v.y = v.y * 0.5f * (1.0f + erff(v.y * INV_SQRT_2F));
                v.z = v.z * 0.5f * (1.0f + erff(v.z * INV_SQRT_2F));
                v.w = v.w * 0.5f * (1.0f + erff(v.w * INV_SQRT_2F));
            }
            *(float4*)&C[(size_t)m * ldc + n] = v;
        }
    }
}

// ---------------- small kernels ----------------
__global__ void build_x_kernel(const int* __restrict__ paths,
                               const float* __restrict__ ego,
                               const float* __restrict__ pos)
{
    int bl = blockIdx.x;
    int c  = threadIdx.x;
    int p  = paths[bl];
    int l  = bl & (Lc - 1);
    g_x[(size_t)bl * Dc + c] = ego[(size_t)p * Dc + c] + pos[l * Dc + c];
    if (c == 0) g_mask[bl] = (p < NUM_TOTAL_C) ? 0.f : -10000.f;
}

// band-pass impulse response c[n] = irfft(mask)[n], in double for exactness
__global__ void build_c_kernel(int left, int right)
{
    int n = threadIdx.x;
    double s = 0.0;
    for (int f = left; f < right; f++) {
        double w;
        if (f == 0)            w = 1.0;
        else if (f == Lc / 2)  w = (n & 1) ? -1.0 : 1.0;
        else                   w = 2.0 * cos(2.0 * M_PI * (double)f * (double)n / (double)Lc);
        s += w;
    }
    g_c[n] = (float)(s / (double)Lc);
}

__global__ void build_C_kernel()
{
    int n = blockIdx.x, m = threadIdx.x;
    g_Cm[n * Lc + m] = g_c[(n - m + Lc) & (Lc - 1)];
}

// mean_value[b,d] = (1/D) sum_{h,n} S[b,h,n,(n-d) mod L]
__global__ void meanv_kernel()
{
    int b   = blockIdx.x;
    int tid = threadIdx.x;          // 512 threads
    int h   = tid >> 8;
    int m   = tid & 255;
    __shared__ float sh[Lc];
    if (tid < Lc) sh[tid] = 0.f;
    __syncthreads();
    const float* Sh = g_S + ((size_t)b * Hc + h) * Lc * Lc;
    for (int n = 0; n < Lc; n++) {
        float v = Sh[(size_t)n * Lc + m];
        atomicAdd(&sh[(n - m + Lc) & (Lc - 1)], v);
    }
    __syncthreads();
    if (tid < Lc) g_mv[b * Lc + tid] = sh[tid] * (1.0f / 128.0f);
}

__global__ void gmean_kernel()
{
    int d = threadIdx.x;
    float s = 0.f;
    for (int b = 0; b < Bc; b++) s += g_mv[b * Lc + d];
    g_gm[d] = s * (1.0f / (float)Bc);
}

// top-5 argmax over 256 values, tie -> lower index
__global__ void topk_kernel()
{
    __shared__ float sv[Lc];
    __shared__ int   si[Lc];
    int t = threadIdx.x;
    float my = g_gm[t];
    for (int it = 0; it < TOPKc; it++) {
        sv[t] = my; si[t] = t;
        __syncthreads();
        for (int s = 128; s > 0; s >>= 1) {
            if (t < s) {
                float v2 = sv[t + s]; int i2 = si[t + s];
                if (v2 > sv[t] || (v2 == sv[t] && i2 < si[t])) { sv[t] = v2; si[t] = i2; }
            }
            __syncthreads();
        }
        int win = si[0];
        if (t == 0) g_delays[it] = win;
        __syncthreads();
        if (t == win) my = -INFINITY;
    }
}

__global__ void wsoft_kernel()
{
    int b = threadIdx.x;   // 256 threads
    float w[TOPKc];
    float mx = -1e30f;
    for (int t = 0; t < TOPKc; t++) {
        w[t] = g_mv[b * Lc + g_delays[t]];
        mx = fmaxf(mx, w[t]);
    }
    float s = 0.f;
    for (int t = 0; t < TOPKc; t++) { w[t] = expf(w[t] - mx); s += w[t]; }
    float inv = 1.0f / s;
    for (int t = 0; t < TOPKc; t++) g_w[b * TOPKc + t] = w[t] * inv;
}

// softmax over key dim (with scale + additive key mask), in place on g_S
__global__ void softmax_kernel()
{
    size_t row = blockIdx.x;                 // (b*H + h)*L + q
    int b = (int)(row / (Hc * Lc));
    float* p = g_S + row * (size_t)Lc;
    int t = threadIdx.x;
    float v = p[t] * INV_SQRT_E + g_mask[b * Lc + t];
    __shared__ float red[Lc];
    red[t] = v; __syncthreads();
    for (int s = 128; s > 0; s >>= 1) { if (t < s) red[t] = fmaxf(red[t], red[t + s]); __syncthreads(); }
    float mx = red[0];
    __syncthreads();
    float e = expf(v - mx);
    red[t] = e; __syncthreads();
    for (int s = 128; s > 0; s >>= 1) { if (t < s) red[t] += red[t + s]; __syncthreads(); }
    float inv = 1.0f / red[0];
    p[t] = e * inv;
}

// out = 0.9 * freq(delay-gathered unfiltered V, weights) + 0.1 * spatial
__global__ void combine_kernel()
{
    int bl = blockIdx.x;
    int c  = threadIdx.x;
    int b  = bl >> 8;
    int l  = bl & 255;
    __shared__ float w[TOPKc];
    __shared__ int   dl[TOPKc];
    if (c < TOPKc) { w[c] = g_w[b * TOPKc + c]; dl[c] = g_delays[c]; }
    __syncthreads();
    float f = 0.f;
    #pragma unroll
    for (int t = 0; t < TOPKc; t++) {
        int ls = (l + dl[t]) & 255;
        f += w[t] * g_vb[((size_t)b * Lc + ls) * Dc + c];
    }
    g_o[(size_t)bl * Dc + c] = 0.9f * f + 0.1f * g_sp[(size_t)bl * Dc + c];
}

__global__ void gather_kernel(const int* __restrict__ lengths, float* __restrict__ out)
{
    int b = blockIdx.x;
    int c = threadIdx.x;
    int l = lengths[b] - 1;
    out[b * Dc + c] = g_x[((size_t)b * Lc + l) * Dc + c];
}

// ---------------- host side ----------------
static inline void launch_gemm(const float* A, const float* Bp, float* C,
                               int M, int N, int K,
                               int lda, int ldb, int ldc,
                               int batch, int zdiv,
                               long sA1, long sA2, long sB1, long sB2, long sC1, long sC2,
                               int transB, int BN,
                               const float* R = nullptr, int ldr = 0, int fuse = 0)
{
    dim3 grid(M / 128, N / BN, batch);
    if (BN == 128)
        sgemm_kernel<128><<<grid, 256>>>(A, Bp, C, M, N, K, lda, ldb, ldc,
                                         zdiv, sA1, sA2, sB1, sB2, sC1, sC2,
                                         transB, R, ldr, fuse);
    else
        sgemm_kernel<64><<<grid, 256>>>(A, Bp, C, M, N, K, lda, ldb, ldc,
                                        zdiv, sA1, sA2, sB1, sB2, sC1, sC2,
                                        transB, R, ldr, fuse);
}

extern "C" void kernel_launch(void* const* d_in, const int* in_sizes, int n_in,
                              void* d_out, int out_size)
{
    (void)in_sizes; (void)n_in; (void)out_size;
    const int*   paths   = (const int*)  d_in[0];
    const int*   lengths = (const int*)  d_in[1];
    const float* ego     = (const float*)d_in[4];
    const float* pos     = (const float*)d_in[5];
    const float* Wq      = (const float*)d_in[6];
    const float* Wk      = (const float*)d_in[7];
    const float* Wv      = (const float*)d_in[8];
    const float* Wp      = (const float*)d_in[9];
    const float* F1      = (const float*)d_in[10];
    const float* F2      = (const float*)d_in[11];
    float* out = (float*)d_out;

    float *px, *pxt, *pv, *pqt, *pkt, *pvt, *pS, *psp, *po, *pa, *ph, *pCm;
    cudaGetSymbolAddress((void**)&px,  g_x);
    cudaGetSymbolAddress((void**)&pxt, g_xt);
    cudaGetSymbolAddress((void**)&pv,  g_vb);
    cudaGetSymbolAddress((void**)&pqt, g_qt);
    cudaGetSymbolAddress((void**)&pkt, g_kt);
    cudaGetSymbolAddress((void**)&pvt, g_vt);
    cudaGetSymbolAddress((void**)&pS,  g_S);
    cudaGetSymbolAddress((void**)&psp, g_sp);
    cudaGetSymbolAddress((void**)&po,  g_o);
    cudaGetSymbolAddress((void**)&pa,  g_a);
    cudaGetSymbolAddress((void**)&ph,  g_h);
    cudaGetSymbolAddress((void**)&pCm, g_Cm);

    const long LD = (long)Lc * Dc;    // 32768
    const long LL = (long)Lc * Lc;    // 65536

    build_x_kernel<<<Bc * Lc, Dc>>>(paths, ego, pos);

    const int lefts[NLc]  = {51, 0};
    const int rights[NLc] = {129, 78};

    for (int k = 0; k < NLc; k++) {
        build_c_kernel<<<1, Lc>>>(lefts[k], rights[k]);
        build_C_kernel<<<Lc, Lc>>>();

        // xt = C @ x   (band filter commutes with linear projections:
        //  C(xW) = (Cx)W, so filter ONCE on x instead of on q,k,v)
        launch_gemm(pCm, px, pxt, Lc, Dc, Lc, Lc, Dc, Dc,
                    Bc, 1, 0, 0, LD, 0, LD, 0, 0, 128);

        // unfiltered V (needed for the delay-gather branch)
        launch_gemm(px, Wv + (size_t)k * Dc * Dc, pv, Bc * Lc, Dc, Dc, Dc, Dc, Dc,
                    1, 1, 0, 0, 0, 0, 0, 0, 0, 128);

        // filtered projections from xt
        launch_gemm(pxt, Wq + (size_t)k * Dc * Dc, pqt, Bc * Lc, Dc, Dc, Dc, Dc, Dc,
                    1, 1, 0, 0, 0, 0, 0, 0, 0, 128);
        launch_gemm(pxt, Wk + (size_t)k * Dc * Dc, pkt, Bc * Lc, Dc, Dc, Dc, Dc, Dc,
                    1, 1, 0, 0, 0, 0, 0, 0, 0, 128);
        launch_gemm(pxt, Wv + (size_t)k * Dc * Dc, pvt, Bc * Lc, Dc, Dc, Dc, Dc, Dc,
                    1, 1, 0, 0, 0, 0, 0, 0, 0, 128);

        // raw scores: per (b,h), Qt(L,E) @ Kt(L,E)^T
        launch_gemm(pqt, pkt, pS, Lc, Lc, Ec, Dc, Dc, Lc,
                    Bc * Hc, Hc, LD, Ec, LD, Ec, (long)Hc * LL, LL, 1, 128);

        // autocorrelation branch (reads raw scores)
        meanv_kernel<<<Bc, 512>>>();
        gmean_kernel<<<1, Lc>>>();
        topk_kernel<<<1, Lc>>>();
        wsoft_kernel<<<1, Bc>>>();

        // attention softmax (in place), then att @ Vt  (N=64 tile)
        softmax_kernel<<<Bc * Hc * Lc, Lc>>>();
        launch_gemm(pS, pvt, psp, Lc, Ec, Lc, Lc, Dc, Dc,
                    Bc * Hc, Hc, (long)Hc * LL, LL, LD, Ec, LD, Ec, 0, 64);

        // freq + spatial mix
        combine_kernel<<<Bc * Lc, Dc>>>();

        // out @ Wp + x (fused residual)
        launch_gemm(po, Wp + (size_t)k * Dc * Dc, pa, Bc * Lc, Dc, Dc, Dc, Dc, Dc,
                    1, 1, 0, 0, 0, 0, 0, 0, 0, 128, px, Dc, 1);

        // FFN: (a @ F1) -> GELU -> (@ F2) -> new x
        launch_gemm(pa, F1 + (size_t)k * Dc * 2 * Dc, ph, Bc * Lc, 2 * Dc, Dc,
                    Dc, 2 * Dc, 2 * Dc, 1, 1, 0, 0, 0, 0, 0, 0, 0, 128,
                    nullptr, 0, 2);
        launch_gemm(ph, F2 + (size_t)k * 2 * Dc * Dc, px, Bc * Lc, Dc, 2 * Dc,
                    2 * Dc, Dc, Dc, 1, 1, 0, 0, 0, 0, 0, 0, 0, 128);
    }

    gather_kernel<<<Bc, Dc>>>(lengths, out);
}

// round 5
// speedup vs baseline: 2.3986x; 1.1190x over previous
#include <cuda_runtime.h>
#include <cuda_bf16.h>
#include <math.h>
#include <stdint.h>

#ifndef M_PI
#define M_PI 3.14159265358979323846
#endif

// Problem constants
#define Bc 256
#define Lc 256
#define Dc 128
#define Hc 2
#define Ec 64
#define NLc 2
#define TOPKc 5
#define NUM_TOTAL_C 100000
#define INV_SQRT_E 0.125f
#define INV_SQRT_2F 0.70710678118654752440f

// ---------------- scratch (static __device__, no allocations) ----------------
// fp32 working set
__device__ float g_x [Bc*Lc*Dc];
__device__ float g_mask[Bc*Lc];
__device__ float g_xt[Bc*Lc*Dc];
__device__ float g_vb[Bc*Lc*Dc];
__device__ float g_qt[Bc*Lc*Dc];
__device__ float g_kt[Bc*Lc*Dc];
__device__ float g_vt[Bc*Lc*Dc];
__device__ float g_S [(size_t)Bc*Hc*Lc*Lc];     // raw scores fp32
__device__ float g_mv[Bc*Lc];
__device__ float g_gm[Lc];
__device__ int   g_delays[TOPKc];
__device__ float g_w [Bc*TOPKc];
__device__ float g_sp[Bc*Lc*Dc];
__device__ float g_o [Bc*Lc*Dc];
__device__ float g_a [Bc*Lc*Dc];
__device__ float g_h [Bc*Lc*2*Dc];
__device__ float g_c [Lc];

// bf16 split (K-tripled) operands
__device__ __nv_bfloat16 g_Cm3 [Lc*3*Lc];                 // A-role (h,h,l) cols
__device__ __nv_bfloat16 g_xA3 [Bc*Lc*3*Dc];              // A-role along D
__device__ __nv_bfloat16 g_xtA3[Bc*Lc*3*Dc];
__device__ __nv_bfloat16 g_xB3 [(size_t)Bc*3*Lc*Dc];      // B-role rows tripled along L
__device__ __nv_bfloat16 g_qt3 [Bc*Lc*3*Dc];              // A-role along D
__device__ __nv_bfloat16 g_kt3 [Bc*Lc*3*Dc];              // B-role (h,l,h) cols (transB)
__device__ __nv_bfloat16 g_vt3 [(size_t)Bc*3*Lc*Dc];      // B-role rows tripled along L
__device__ __nv_bfloat16 g_S3  [(size_t)Bc*Hc*Lc*3*Lc];   // A-role along key dim
__device__ __nv_bfloat16 g_o3  [Bc*Lc*3*Dc];
__device__ __nv_bfloat16 g_a3  [Bc*Lc*3*Dc];
__device__ __nv_bfloat16 g_h3  [(size_t)Bc*Lc*3*2*Dc];
__device__ __nv_bfloat16 g_W3  [6*3*Dc*2*Dc];             // per-layer weight scratch

// weight scratch offsets (elements)
#define W3_Q  0
#define W3_K  (3*Dc*Dc)
#define W3_V  (2*3*Dc*Dc)
#define W3_P  (3*3*Dc*Dc)
#define W3_F1 (4*3*Dc*Dc)
#define W3_F2 (4*3*Dc*Dc + 3*Dc*2*Dc)

// ---------------- helpers ----------------
__device__ __forceinline__ uint32_t smem_u32(const void* p) {
    return (uint32_t)__cvta_generic_to_shared(p);
}
__device__ __forceinline__ void cpasync16(void* sp, const void* gp) {
    asm volatile("cp.async.cg.shared.global [%0], [%1], 16;"
                 :: "r"(smem_u32(sp)), "l"(gp));
}
#define CP_COMMIT() asm volatile("cp.async.commit_group;")
#define CP_WAIT0()  asm volatile("cp.async.wait_group 0;")

#define LDSM_X4(r0,r1,r2,r3,addr) \
    asm volatile("ldmatrix.sync.aligned.m8n8.x4.shared.b16 {%0,%1,%2,%3}, [%4];" \
        : "=r"(r0),"=r"(r1),"=r"(r2),"=r"(r3) : "r"(addr))
#define LDSM_X4_T(r0,r1,r2,r3,addr) \
    asm volatile("ldmatrix.sync.aligned.m8n8.x4.trans.shared.b16 {%0,%1,%2,%3}, [%4];" \
        : "=r"(r0),"=r"(r1),"=r"(r2),"=r"(r3) : "r"(addr))

#define MMA_BF16(d, a, b0v, b1v) \
    asm volatile("mma.sync.aligned.m16n8k16.row.col.f32.bf16.bf16.f32 " \
        "{%0,%1,%2,%3}, {%4,%5,%6,%7}, {%8,%9}, {%0,%1,%2,%3};" \
        : "+f"(d[0]), "+f"(d[1]), "+f"(d[2]), "+f"(d[3]) \
        : "r"(a[0]), "r"(a[1]), "r"(a[2]), "r"(a[3]), "r"(b0v), "r"(b1v))

// ---------------- bf16x3 tensor-core GEMM ----------------
// C[m,n] (fp32) = sum_k A3[m,k]*B3[k or n...], K is the TRIPLED K.
// A3: [M, K] bf16 row-major.  B3: TB ? [N, K] : [K, N] bf16 row-major.
// Block tile 128 x BN, 8 warps, BK=32, cp.async double-buffered.
// fuse: 0 none, 1 += R[m,n], 2 exact-erf GELU.
template<int BN, bool TB>
__global__ __launch_bounds__(256, 2)
void mma_kernel(const __nv_bfloat16* __restrict__ A,
                const __nv_bfloat16* __restrict__ Bp,
                float* __restrict__ C,
                int K, int lda, int ldb, int ldc,
                int zdiv, long sA1, long sA2, long sB1, long sB2, long sC1, long sC2,
                const float* __restrict__ R, int ldr, int fuse)
{
    constexpr int WM   = (BN == 128) ? 64 : 32;
    constexpr int MT   = WM / 16;          // 4 or 2
    constexpr int NT16 = 2;                // WN = 32 always
    constexpr int BK   = 32;

    const int tid  = threadIdx.x;
    const int warp = tid >> 5;
    const int lane = tid & 31;
    int warpM0, warpN0;
    if (BN == 128) { warpM0 = (warp & 1) * 64; warpN0 = (warp >> 1) * 32; }
    else           { warpM0 = (warp & 3) * 32; warpN0 = (warp >> 2) * 32; }

    int z = blockIdx.z, z1 = z / zdiv, z2 = z - z1 * zdiv;
    A  += z1 * sA1 + z2 * sA2;
    Bp += z1 * sB1 + z2 * sB2;
    C  += z1 * sC1 + z2 * sC2;

    const int m0 = blockIdx.x * 128;
    const int n0 = blockIdx.y * BN;

    __shared__ __nv_bfloat16 As[2][128][BK + 8];
    constexpr int BROWS = TB ? BN : BK;
    constexpr int BCOLS = TB ? (BK + 8) : (BN + 8);
    __shared__ __nv_bfloat16 Bs[2][BROWS][BCOLS];

    auto load_tiles = [&](int buf, int k0) {
        // A: 128 rows x 32 cols = 512 16B chunks
        #pragma unroll
        for (int i = 0; i < 2; i++) {
            int c = tid + i * 256;
            int row = c >> 2, kc = (c & 3) << 3;
            cpasync16(&As[buf][row][kc],
                      A + (size_t)(m0 + row) * lda + k0 + kc);
        }
        if (TB) {
            constexpr int BCH = BN * 4;
            #pragma unroll
            for (int i = 0; i < BCH / 256; i++) {
                int c = tid + i * 256;
                int row = c >> 2, kc = (c & 3) << 3;
                cpasync16(&Bs[buf][row][kc],
                          Bp + (size_t)(n0 + row) * ldb + k0 + kc);
            }
        } else {
            constexpr int CPR = BN / 8;
            constexpr int BCH = 32 * CPR;
            #pragma unroll
            for (int i = 0; i < BCH / 256; i++) {
                int c = tid + i * 256;
                int row = c / CPR, nc = (c % CPR) << 3;
                cpasync16(&Bs[buf][row][nc],
                          Bp + (size_t)(k0 + row) * ldb + n0 + nc);
            }
        }
    };

    float acc[MT][NT16][2][4];
    #pragma unroll
    for (int i = 0; i < MT; i++)
        #pragma unroll
        for (int j = 0; j < NT16; j++)
            #pragma unroll
            for (int s = 0; s < 2; s++)
                #pragma unroll
                for (int q = 0; q < 4; q++) acc[i][j][s][q] = 0.f;

    const int nk = K / BK;
    load_tiles(0, 0);
    CP_COMMIT();

    int buf = 0;
    for (int kt = 0; kt < nk; kt++) {
        CP_WAIT0();
        __syncthreads();
        if (kt + 1 < nk) {
            load_tiles(buf ^ 1, (kt + 1) * BK);
            CP_COMMIT();
        }
        // compute current buffer
        #pragma unroll
        for (int ks = 0; ks < 2; ks++) {
            uint32_t a[MT][4];
            #pragma unroll
            for (int tm = 0; tm < MT; tm++) {
                uint32_t addr = smem_u32(
                    &As[buf][warpM0 + tm*16 + (lane & 15)][ks*16 + ((lane >> 4) << 3)]);
                LDSM_X4(a[tm][0], a[tm][1], a[tm][2], a[tm][3], addr);
            }
            uint32_t b[NT16][4];
            #pragma unroll
            for (int tn = 0; tn < NT16; tn++) {
                if (TB) {
                    uint32_t addr = smem_u32(
                        &Bs[buf][warpN0 + tn*16 + (lane & 15)][ks*16 + ((lane >> 4) << 3)]);
                    LDSM_X4(b[tn][0], b[tn][1], b[tn][2], b[tn][3], addr);
                } else {
                    uint32_t addr = smem_u32(
                        &Bs[buf][ks*16 + (lane & 15)][warpN0 + tn*16 + ((lane >> 4) << 3)]);
                    LDSM_X4_T(b[tn][0], b[tn][1], b[tn][2], b[tn][3], addr);
                }
            }
            #pragma unroll
            for (int tm = 0; tm < MT; tm++)
                #pragma unroll
                for (int tn = 0; tn < NT16; tn++) {
                    if (TB) {
                        MMA_BF16(acc[tm][tn][0], a[tm], b[tn][0], b[tn][2]);
                        MMA_BF16(acc[tm][tn][1], a[tm], b[tn][1], b[tn][3]);
                    } else {
                        MMA_BF16(acc[tm][tn][0], a[tm], b[tn][0], b[tn][1]);
                        MMA_BF16(acc[tm][tn][1], a[tm], b[tn][2], b[tn][3]);
                    }
                }
        }
        buf ^= 1;
    }

    // epilogue
    #pragma unroll
    for (int tm = 0; tm < MT; tm++)
        #pragma unroll
        for (int tn = 0; tn < NT16; tn++)
            #pragma unroll
            for (int s = 0; s < 2; s++) {
                int col = n0 + warpN0 + tn*16 + s*8 + ((lane & 3) << 1);
                float* cc = acc[tm][tn][s];
                #pragma unroll
                for (int hr = 0; hr < 2; hr++) {
                    int row = m0 + warpM0 + tm*16 + (lane >> 2) + hr*8;
                    float2 v = make_float2(cc[hr*2 + 0], cc[hr*2 + 1]);
                    if (fuse == 1) {
                        float2 r = *(const float2*)&R[(size_t)row * ldr + col];
                        v.x += r.x; v.y += r.y;
                    } else if (fuse == 2) {
                        v.x = v.x * 0.5f * (1.0f + erff(v.x * INV_SQRT_2F));
                        v.y = v.y * 0.5f * (1.0f + erff(v.y * INV_SQRT_2F));
                    }
                    *(float2*)&C[(size_t)row * ldc + col] = v;
                }
            }
}

// ---------------- split-conversion kernels ----------------
// PAT 0: A-role (h,h,l) along cols ; PAT 1: B-role transB (h,l,h) along cols
template<int PAT>
__global__ void conv_cols3(const float* __restrict__ in,
                           __nv_bfloat16* __restrict__ out, int K)
{
    size_t idx = (size_t)blockIdx.x * 256 + threadIdx.x;
    size_t r = idx / (unsigned)K;
    int   k = (int)(idx - r * (unsigned)K);
    float v = in[idx];
    __nv_bfloat16 h = __float2bfloat16(v);
    __nv_bfloat16 l = __float2bfloat16(v - __bfloat162float(h));
    __nv_bfloat16* o = out + r * (size_t)(3 * K) + 3 * k;
    if (PAT == 0) { o[0] = h; o[1] = h; o[2] = l; }
    else          { o[0] = h; o[1] = l; o[2] = h; }
}

// B-role NN: rows tripled (h,l,h)
__global__ void conv_rows3(const float* __restrict__ in,
                           __nv_bfloat16* __restrict__ out, int N)
{
    size_t idx = (size_t)blockIdx.x * 256 + threadIdx.x;
    size_t r = idx / (unsigned)N;
    int   n = (int)(idx - r * (unsigned)N);
    float v = in[idx];
    __nv_bfloat16 h = __float2bfloat16(v);
    __nv_bfloat16 l = __float2bfloat16(v - __bfloat162float(h));
    __nv_bfloat16* o = out + (3 * r) * (size_t)N + n;
    o[0]           = h;
    o[(size_t)N]   = l;
    o[(size_t)2*N] = h;
}

// ---------------- small kernels ----------------
__global__ void build_x_kernel(const int* __restrict__ paths,
                               const float* __restrict__ ego,
                               const float* __restrict__ pos)
{
    int bl = blockIdx.x;
    int c  = threadIdx.x;
    int p  = paths[bl];
    int l  = bl & (Lc - 1);
    g_x[(size_t)bl * Dc + c] = ego[(size_t)p * Dc + c] + pos[l * Dc + c];
    if (c == 0) g_mask[bl] = (p < NUM_TOTAL_C) ? 0.f : -10000.f;
}

__global__ void build_c_kernel(int left, int right)
{
    int n = threadIdx.x;
    double s = 0.0;
    for (int f = left; f < right; f++) {
        double w;
        if (f == 0)            w = 1.0;
        else if (f == Lc / 2)  w = (n & 1) ? -1.0 : 1.0;
        else                   w = 2.0 * cos(2.0 * M_PI * (double)f * (double)n / (double)Lc);
        s += w;
    }
    g_c[n] = (float)(s / (double)Lc);
}

// Cm3[n][3m+{0,1,2}] = (h,h,l) of c[(n-m) mod L]   (A-role)
__global__ void build_C3_kernel()
{
    int n = blockIdx.x, m = threadIdx.x;
    float v = g_c[(n - m + Lc) & (Lc - 1)];
    __nv_bfloat16 h = __float2bfloat16(v);
    __nv_bfloat16 l = __float2bfloat16(v - __bfloat162float(h));
    __nv_bfloat16* o = g_Cm3 + (size_t)n * (3 * Lc) + 3 * m;
    o[0] = h; o[1] = h; o[2] = l;
}

__global__ void meanv_kernel()
{
    int b   = blockIdx.x;
    int tid = threadIdx.x;          // 512 threads
    int h   = tid >> 8;
    int m   = tid & 255;
    __shared__ float sh[Lc];
    if (tid < Lc) sh[tid] = 0.f;
    __syncthreads();
    const float* Sh = g_S + ((size_t)b * Hc + h) * Lc * Lc;
    for (int n = 0; n < Lc; n++) {
        float v = Sh[(size_t)n * Lc + m];
        atomicAdd(&sh[(n - m + Lc) & (Lc - 1)], v);
    }
    __syncthreads();
    if (tid < Lc) g_mv[b * Lc + tid] = sh[tid] * (1.0f / 128.0f);
}

__global__ void gmean_kernel()
{
    int d = threadIdx.x;
    float s = 0.f;
    for (int b = 0; b < Bc; b++) s += g_mv[b * Lc + d];
    g_gm[d] = s * (1.0f / (float)Bc);
}

__global__ void topk_kernel()
{
    __shared__ float sv[Lc];
    __shared__ int   si[Lc];
    int t = threadIdx.x;
    float my = g_gm[t];
    for (int it = 0; it < TOPKc; it++) {
        sv[t] = my; si[t] = t;
        __syncthreads();
        for (int s = 128; s > 0; s >>= 1) {
            if (t < s) {
                float v2 = sv[t + s]; int i2 = si[t + s];
                if (v2 > sv[t] || (v2 == sv[t] && i2 < si[t])) { sv[t] = v2; si[t] = i2; }
            }
            __syncthreads();
        }
        int win = si[0];
        if (t == 0) g_delays[it] = win;
        __syncthreads();
        if (t == win) my = -INFINITY;
    }
}

__global__ void wsoft_kernel()
{
    int b = threadIdx.x;
    float w[TOPKc];
    float mx = -1e30f;
    for (int t = 0; t < TOPKc; t++) {
        w[t] = g_mv[b * Lc + g_delays[t]];
        mx = fmaxf(mx, w[t]);
    }
    float s = 0.f;
    for (int t = 0; t < TOPKc; t++) { w[t] = expf(w[t] - mx); s += w[t]; }
    float inv = 1.0f / s;
    for (int t = 0; t < TOPKc; t++) g_w[b * TOPKc + t] = w[t] * inv;
}

// softmax over key dim; reads raw fp32 S, writes bf16 split triple (A-role) to S3
__global__ void softmax3_kernel()
{
    size_t row = blockIdx.x;                 // (b*H + h)*L + q
    int b = (int)(row / (Hc * Lc));
    const float* p = g_S + row * (size_t)Lc;
    int t = threadIdx.x;
    float v = p[t] * INV_SQRT_E + g_mask[b * Lc + t];
    __shared__ float red[Lc];
    red[t] = v; __syncthreads();
    for (int s = 128; s > 0; s >>= 1) { if (t < s) red[t] = fmaxf(red[t], red[t + s]); __syncthreads(); }
    float mx = red[0];
    __syncthreads();
    float e = expf(v - mx);
    red[t] = e; __syncthreads();
    for (int s = 128; s > 0; s >>= 1) { if (t < s) red[t] += red[t + s]; __syncthreads(); }
    float att = e / red[0];
    __nv_bfloat16 h = __float2bfloat16(att);
    __nv_bfloat16 l = __float2bfloat16(att - __bfloat162float(h));
    __nv_bfloat16* o = g_S3 + row * (size_t)(3 * Lc) + 3 * t;
    o[0] = h; o[1] = h; o[2] = l;
}

__global__ void combine_kernel()
{
    int bl = blockIdx.x;
    int c  = threadIdx.x;
    int b  = bl >> 8;
    int l  = bl & 255;
    __shared__ float w[TOPKc];
    __shared__ int   dl[TOPKc];
    if (c < TOPKc) { w[c] = g_w[b * TOPKc + c]; dl[c] = g_delays[c]; }
    __syncthreads();
    float f = 0.f;
    #pragma unroll
    for (int t = 0; t < TOPKc; t++) {
        int ls = (l + dl[t]) & 255;
        f += w[t] * g_vb[((size_t)b * Lc + ls) * Dc + c];
    }
    g_o[(size_t)bl * Dc + c] = 0.9f * f + 0.1f * g_sp[(size_t)bl * Dc + c];
}

__global__ void gather_kernel(const int* __restrict__ lengths, float* __restrict__ out)
{
    int b = blockIdx.x;
    int c = threadIdx.x;
    int l = lengths[b] - 1;
    out[b * Dc + c] = g_x[((size_t)b * Lc + l) * Dc + c];
}

// ---------------- host side ----------------
typedef __nv_bfloat16 bf16;

static inline void launch_mma(int BN, bool TB,
                              const bf16* A, const bf16* B, float* C,
                              int M, int N, int K,
                              int lda, int ldb, int ldc,
                              int batch, int zdiv,
                              long sA1, long sA2, long sB1, long sB2, long sC1, long sC2,
                              const float* R = nullptr, int ldr = 0, int fuse = 0)
{
    dim3 grid(M / 128, N / BN, batch);
    if (BN == 128 && !TB)
        mma_kernel<128,false><<<grid, 256>>>(A, B, C, K, lda, ldb, ldc,
            zdiv, sA1, sA2, sB1, sB2, sC1, sC2, R, ldr, fuse);
    else if (BN == 128 && TB)
        mma_kernel<128,true><<<grid, 256>>>(A, B, C, K, lda, ldb, ldc,
            zdiv, sA1, sA2, sB1, sB2, sC1, sC2, R, ldr, fuse);
    else
        mma_kernel<64,false><<<grid, 256>>>(A, B, C, K, lda, ldb, ldc,
            zdiv, sA1, sA2, sB1, sB2, sC1, sC2, R, ldr, fuse);
}

extern "C" void kernel_launch(void* const* d_in, const int* in_sizes, int n_in,
                              void* d_out, int out_size)
{
    (void)in_sizes; (void)n_in; (void)out_size;
    const int*   paths   = (const int*)  d_in[0];
    const int*   lengths = (const int*)  d_in[1];
    const float* ego     = (const float*)d_in[4];
    const float* pos     = (const float*)d_in[5];
    const float* Wq      = (const float*)d_in[6];
    const float* Wk      = (const float*)d_in[7];
    const float* Wv      = (const float*)d_in[8];
    const float* Wp      = (const float*)d_in[9];
    const float* F1      = (const float*)d_in[10];
    const float* F2      = (const float*)d_in[11];
    float* out = (float*)d_out;

    float *px, *pxt, *pvb, *pqt, *pkt, *pvt, *pS, *psp, *po, *pa, *ph;
    bf16 *pCm3, *pxA3, *pxtA3, *pxB3, *pqt3, *pkt3, *pvt3, *pS3, *po3, *pa3, *ph3, *pW3;
    cudaGetSymbolAddress((void**)&px,   g_x);
    cudaGetSymbolAddress((void**)&pxt,  g_xt);
    cudaGetSymbolAddress((void**)&pvb,  g_vb);
    cudaGetSymbolAddress((void**)&pqt,  g_qt);
    cudaGetSymbolAddress((void**)&pkt,  g_kt);
    cudaGetSymbolAddress((void**)&pvt,  g_vt);
    cudaGetSymbolAddress((void**)&pS,   g_S);
    cudaGetSymbolAddress((void**)&psp,  g_sp);
    cudaGetSymbolAddress((void**)&po,   g_o);
    cudaGetSymbolAddress((void**)&pa,   g_a);
    cudaGetSymbolAddress((void**)&ph,   g_h);
    cudaGetSymbolAddress((void**)&pCm3, g_Cm3);
    cudaGetSymbolAddress((void**)&pxA3, g_xA3);
    cudaGetSymbolAddress((void**)&pxtA3,g_xtA3);
    cudaGetSymbolAddress((void**)&pxB3, g_xB3);
    cudaGetSymbolAddress((void**)&pqt3, g_qt3);
    cudaGetSymbolAddress((void**)&pkt3, g_kt3);
    cudaGetSymbolAddress((void**)&pvt3, g_vt3);
    cudaGetSymbolAddress((void**)&pS3,  g_S3);
    cudaGetSymbolAddress((void**)&po3,  g_o3);
    cudaGetSymbolAddress((void**)&pa3,  g_a3);
    cudaGetSymbolAddress((void**)&ph3,  g_h3);
    cudaGetSymbolAddress((void**)&pW3,  g_W3);

    const int  BL   = Bc * Lc;                 // 65536 rows
    const long LD   = (long)Lc * Dc;           // 32768
    const long LL   = (long)Lc * Lc;           // 65536
    const long L3D  = (long)Lc * 3 * Dc;       // 98304  (A-role act stride / batch)
    const long S3B  = (long)Lc * 3 * Lc;       // 196608 (S3 per (b,h))

    build_x_kernel<<<BL, Dc>>>(paths, ego, pos);

    const int lefts[NLc]  = {51, 0};
    const int rights[NLc] = {129, 78};

    for (int k = 0; k < NLc; k++) {
        build_c_kernel<<<1, Lc>>>(lefts[k], rights[k]);
        build_C3_kernel<<<Lc, Lc>>>();

        // weight splits (B-role NN, rows tripled)
        conv_rows3<<<Dc*Dc/256, 256>>>(Wq + (size_t)k*Dc*Dc, pW3 + W3_Q,  Dc);
        conv_rows3<<<Dc*Dc/256, 256>>>(Wk + (size_t)k*Dc*Dc, pW3 + W3_K,  Dc);
        conv_rows3<<<Dc*Dc/256, 256>>>(Wv + (size_t)k*Dc*Dc, pW3 + W3_V,  Dc);
        conv_rows3<<<Dc*Dc/256, 256>>>(Wp + (size_t)k*Dc*Dc, pW3 + W3_P,  Dc);
        conv_rows3<<<Dc*2*Dc/256, 256>>>(F1 + (size_t)k*Dc*2*Dc, pW3 + W3_F1, 2*Dc);
        conv_rows3<<<2*Dc*Dc/256, 256>>>(F2 + (size_t)k*2*Dc*Dc, pW3 + W3_F2, Dc);

        // x splits: B-role along L (for xt GEMM) and A-role along D (for vb)
        conv_rows3<<<BL*Dc/256, 256>>>(px, pxB3, Dc);
        conv_cols3<0><<<BL*Dc/256, 256>>>(px, pxA3, Dc);

        // xt = Cm @ x   (per batch: A=Cm3 [256,768], B=xB3 [768,128])
        launch_mma(128, false, pCm3, pxB3, pxt, Lc, Dc, 3*Lc, 3*Lc, Dc, Dc,
                   Bc, 1, 0, 0, 3*LD, 0, LD, 0);

        conv_cols3<0><<<BL*Dc/256, 256>>>(pxt, pxtA3, Dc);

        // vb = x @ Wv (unfiltered V)
        launch_mma(128, false, pxA3, pW3 + W3_V, pvb, BL, Dc, 3*Dc, 3*Dc, Dc, Dc,
                   1, 1, 0, 0, 0, 0, 0, 0);
        // filtered projections
        launch_mma(128, false, pxtA3, pW3 + W3_Q, pqt, BL, Dc, 3*Dc, 3*Dc, Dc, Dc,
                   1, 1, 0, 0, 0, 0, 0, 0);
        launch_mma(128, false, pxtA3, pW3 + W3_K, pkt, BL, Dc, 3*Dc, 3*Dc, Dc, Dc,
                   1, 1, 0, 0, 0, 0, 0, 0);
        launch_mma(128, false, pxtA3, pW3 + W3_V, pvt, BL, Dc, 3*Dc, 3*Dc, Dc, Dc,
                   1, 1, 0, 0, 0, 0, 0, 0);

        // splits for attention
        conv_cols3<0><<<BL*Dc/256, 256>>>(pqt, pqt3, Dc);   // A-role
        conv_cols3<1><<<BL*Dc/256, 256>>>(pkt, pkt3, Dc);   // B-role transB
        conv_rows3  <<<BL*Dc/256, 256>>>(pvt, pvt3, Dc);    // B-role NN along L

        // raw scores: per (b,h): Qt3[256,192(head)] @ Kt3[256,192]^T  -> S fp32
        launch_mma(128, true, pqt3, pkt3, pS, Lc, Lc, 3*Ec, 3*Dc, 3*Dc, Lc,
                   Bc * Hc, Hc, L3D, 3*Ec, L3D, 3*Ec, (long)Hc * LL, LL);

        // autocorrelation branch
        meanv_kernel<<<Bc, 512>>>();
        gmean_kernel<<<1, Lc>>>();
        topk_kernel<<<1, Lc>>>();
        wsoft_kernel<<<1, Bc>>>();

        // softmax -> S3 (bf16 triple), then att @ Vt
        softmax3_kernel<<<Bc * Hc * Lc, Lc>>>();
        launch_mma(64, false, pS3, pvt3, psp, Lc, Ec, 3*Lc, 3*Lc, Dc, Dc,
                   Bc * Hc, Hc, (long)Hc * S3B, S3B, 3*LD, Ec, LD, Ec);

        // freq + spatial mix
        combine_kernel<<<BL, Dc>>>();

        // o @ Wp + x (fused residual)
        conv_cols3<0><<<BL*Dc/256, 256>>>(po, po3, Dc);
        launch_mma(128, false, po3, pW3 + W3_P, pa, BL, Dc, 3*Dc, 3*Dc, Dc, Dc,
                   1, 1, 0, 0, 0, 0, 0, 0, px, Dc, 1);

        // FFN: (a @ F1) -> GELU -> (@ F2) -> new x
        conv_cols3<0><<<BL*Dc/256, 256>>>(pa, pa3, Dc);
        launch_mma(128, false, pa3, pW3 + W3_F1, ph, BL, 2*Dc, 3*Dc, 3*Dc, 2*Dc, 2*Dc,
                   1, 1, 0, 0, 0, 0, 0, 0, nullptr, 0, 2);
        conv_cols3<0><<<BL*2*Dc/256, 256>>>(ph, ph3, 2*Dc);
        launch_mma(128, false, ph3, pW3 + W3_F2, px, BL, Dc, 3*2*Dc, 3*2*Dc, Dc, Dc,
                   1, 1, 0, 0, 0, 0, 0, 0);
    }

    gather_kernel<<<Bc, Dc>>>(lengths, out);
}